// round 2
// baseline (speedup 1.0000x reference)
#include <cuda_runtime.h>
#include <math.h>
#include <stdint.h>

#define NN_MAX 100000
#define ADIM   1000
#define JAX_PARTITIONABLE 1   // set 0 to switch to pre-partitionable threefry layout

// ------------------------- scratch (no runtime alloc) -----------------------
__device__ float g_h   [(size_t)NN_MAX*128];
__device__ float g_agg [(size_t)NN_MAX*128];
__device__ float g_h1  [(size_t)NN_MAX*256];
__device__ float g_h2  [(size_t)NN_MAX*256];
__device__ float g_deg [NN_MAX];
__device__ float g_dinv[NN_MAX];
__device__ float g_conc[NN_MAX];
__device__ float g_lg  [NN_MAX];

// ------------------------- threefry2x32 (JAX-exact) -------------------------
struct K2 { unsigned a, b; };

__device__ __forceinline__ void tf_round(unsigned &x0, unsigned &x1, int r) {
    x0 += x1;
    x1 = (x1 << r) | (x1 >> (32 - r));
    x1 ^= x0;
}
__device__ __forceinline__ K2 tf_block(unsigned k0, unsigned k1, unsigned x0, unsigned x1) {
    unsigned k2 = k0 ^ k1 ^ 0x1BD11BDAu;
    x0 += k0; x1 += k1;
    tf_round(x0,x1,13); tf_round(x0,x1,15); tf_round(x0,x1,26); tf_round(x0,x1,6);
    x0 += k1; x1 += k2 + 1u;
    tf_round(x0,x1,17); tf_round(x0,x1,29); tf_round(x0,x1,16); tf_round(x0,x1,24);
    x0 += k2; x1 += k0 + 2u;
    tf_round(x0,x1,13); tf_round(x0,x1,15); tf_round(x0,x1,26); tf_round(x0,x1,6);
    x0 += k0; x1 += k1 + 3u;
    tf_round(x0,x1,17); tf_round(x0,x1,29); tf_round(x0,x1,16); tf_round(x0,x1,24);
    x0 += k1; x1 += k2 + 4u;
    tf_round(x0,x1,13); tf_round(x0,x1,15); tf_round(x0,x1,26); tf_round(x0,x1,6);
    x0 += k2; x1 += k0 + 5u;
    K2 r; r.a = x0; r.b = x1; return r;
}

#if JAX_PARTITIONABLE
// scalar uniform bits: counts (0,0), fold out0^out1
__device__ __forceinline__ unsigned rbits(K2 k) {
    K2 r = tf_block(k.a, k.b, 0u, 0u);
    return r.a ^ r.b;
}
__device__ __forceinline__ void split2(K2 k, K2 &o0, K2 &o1) {
    o0 = tf_block(k.a, k.b, 0u, 0u);
    o1 = tf_block(k.a, k.b, 0u, 1u);
}
__device__ __forceinline__ void split3(K2 k, K2 &o0, K2 &o1, K2 &o2) {
    o0 = tf_block(k.a, k.b, 0u, 0u);
    o1 = tf_block(k.a, k.b, 0u, 1u);
    o2 = tf_block(k.a, k.b, 0u, 2u);
}
__device__ __forceinline__ K2 split_big(K2 k, unsigned i, unsigned n) {
    (void)n; return tf_block(k.a, k.b, 0u, i);
}
#else
// original threefry layout: threefry_2x32(key, iota(2n)) reshaped (n,2)
__device__ __forceinline__ unsigned rbits(K2 k) {        // shape () -> pad, take out0
    K2 r = tf_block(k.a, k.b, 0u, 0u);
    return r.a;
}
__device__ __forceinline__ void split2(K2 k, K2 &o0, K2 &o1) {
    K2 p = tf_block(k.a, k.b, 0u, 2u);   // counts (0,2) -> (a0, b0)
    K2 q = tf_block(k.a, k.b, 1u, 3u);   // counts (1,3) -> (a1, b1)
    o0.a = p.a; o0.b = q.a;              // (out[0],out[1]) = (a0,a1)
    o1.a = p.b; o1.b = q.b;              // (out[2],out[3]) = (b0,b1)
}
__device__ __forceinline__ void split3(K2 k, K2 &o0, K2 &o1, K2 &o2) {
    K2 p = tf_block(k.a, k.b, 0u, 3u);   // (a0,b0)
    K2 q = tf_block(k.a, k.b, 1u, 4u);   // (a1,b1)
    K2 s = tf_block(k.a, k.b, 2u, 5u);   // (a2,b2)
    o0.a = p.a; o0.b = q.a;              // (a0,a1)
    o1.a = s.a; o1.b = p.b;              // (a2,b0)
    o2.a = q.b; o2.b = s.b;              // (b1,b2)
}
__device__ __forceinline__ K2 split_big(K2 k, unsigned i, unsigned n) {
    // out = concat(out0(j), out1(j)), pair j uses counts (j, j+n); subkey_i = (out[2i], out[2i+1])
    unsigned i0 = 2u*i, i1 = 2u*i + 1u;
    K2 r;
    if (i0 < n) { K2 t = tf_block(k.a, k.b, i0, i0 + n); r.a = t.a; }
    else        { K2 t = tf_block(k.a, k.b, i0 - n, i0); r.a = t.b; }
    if (i1 < n) { K2 t = tf_block(k.a, k.b, i1, i1 + n); r.b = t.a; }
    else        { K2 t = tf_block(k.a, k.b, i1 - n, i1); r.b = t.b; }
    return r;
}
#endif

__device__ __forceinline__ float u01(K2 k) {
    unsigned bits = rbits(k);
    return __uint_as_float((bits >> 9) | 0x3f800000u) - 1.0f;   // [0,1)
}

// XLA ErfInv32 polynomial
__device__ __forceinline__ float erfinv_xla(float x) {
    float xx = __fmul_rn(x, x);
    float w = (float)(-log1p(-(double)xx));
    float p;
    if (w < 5.0f) {
        w = __fsub_rn(w, 2.5f);
        p = 2.81022636e-08f;
        p = fmaf(p, w, 3.43273939e-07f);
        p = fmaf(p, w, -3.5233877e-06f);
        p = fmaf(p, w, -4.39150654e-06f);
        p = fmaf(p, w, 0.00021858087f);
        p = fmaf(p, w, -0.00125372503f);
        p = fmaf(p, w, -0.00417768164f);
        p = fmaf(p, w, 0.246640727f);
        p = fmaf(p, w, 1.50140941f);
    } else {
        w = __fsub_rn(__fsqrt_rn(w), 3.0f);
        p = -0.000200214257f;
        p = fmaf(p, w, 0.000100950558f);
        p = fmaf(p, w, 0.00134934322f);
        p = fmaf(p, w, -0.00367342844f);
        p = fmaf(p, w, 0.00573950773f);
        p = fmaf(p, w, -0.0076224613f);
        p = fmaf(p, w, 0.00943887047f);
        p = fmaf(p, w, 1.00167406f);
        p = fmaf(p, w, 2.83297682f);
    }
    return __fmul_rn(p, x);
}

// jax.random.normal scalar: u in [nextafter(-1,0), 1), sqrt(2)*erfinv(u)
__device__ __forceinline__ float nrm(K2 k) {
    float f = u01(k);
    const float lo = __uint_as_float(0xBF7FFFFFu);
    float v = __fadd_rn(__fmul_rn(f, 2.0f), lo);   // (hi-lo) rounds to 2.0f
    v = fmaxf(lo, v);
    return __fmul_rn(__uint_as_float(0x3FB504F3u), erfinv_xla(v));
}

// ------------------------- degree / norm ------------------------------------
__global__ void k_deg_init(int n) {
    int i = blockIdx.x * blockDim.x + threadIdx.x;
    if (i < n) g_deg[i] = 1.0f;                    // self loop
}
__global__ void k_deg_count(const int* __restrict__ dst, int E) {
    int e = blockIdx.x * blockDim.x + threadIdx.x;
    if (e < E) atomicAdd(&g_deg[dst[e]], 1.0f);
}
__global__ void k_dinv(int n) {
    int i = blockIdx.x * blockDim.x + threadIdx.x;
    if (i < n) g_dinv[i] = (float)(1.0 / sqrt((double)g_deg[i]));
}

// self-loop init: agg[i] = h[i] * dinv[i]^2
__global__ void k_self(int n4) {      // n4 = N * 32 (float4 count)
    int idx = blockIdx.x * blockDim.x + threadIdx.x;
    if (idx >= n4) return;
    int node = idx >> 5;
    float di = g_dinv[node];
    float n2 = __fmul_rn(di, di);
    float4 v = ((const float4*)g_h)[idx];
    float4 o;
    o.x = __fmul_rn(v.x, n2); o.y = __fmul_rn(v.y, n2);
    o.z = __fmul_rn(v.z, n2); o.w = __fmul_rn(v.w, n2);
    ((float4*)g_agg)[idx] = o;
}

// edge scatter: one warp per edge
__global__ void k_scatter(const int* __restrict__ src, const int* __restrict__ dst, int E) {
    int e = blockIdx.x * 8 + (threadIdx.x >> 5);
    if (e >= E) return;
    int lane = threadIdx.x & 31;
    int s = __ldg(&src[e]);
    int d = __ldg(&dst[e]);
    float norm = __fmul_rn(g_dinv[s], g_dinv[d]);
    float4 v = *(const float4*)(g_h + (size_t)s * 128 + lane * 4);
    float* out = g_agg + (size_t)d * 128 + lane * 4;
    atomicAdd(out + 0, __fmul_rn(v.x, norm));
    atomicAdd(out + 1, __fmul_rn(v.y, norm));
    atomicAdd(out + 2, __fmul_rn(v.z, norm));
    atomicAdd(out + 3, __fmul_rn(v.w, norm));
}

// ------------------------- GEMMs --------------------------------------------
// MODE 0: g_h  = x @ Wc                 (K=128, COLS=128, no epilogue)
// MODE 1: g_h1 = leaky((relu(agg+bc)+x) @ W1 + b1)   (K=128, COLS=256)
// MODE 2: g_h2 = leaky(h1 @ W2 + b2)    (K=256, COLS=256)
template<int MODE>
__global__ void __launch_bounds__(256) k_gemm(const float* __restrict__ A0,
                                              const float* __restrict__ A1,
                                              const float* __restrict__ bin,
                                              const float* __restrict__ W,
                                              const float* __restrict__ bout,
                                              float* __restrict__ Cout, int N) {
    extern __shared__ float sm[];
    float* sW = sm;                 // 128 x 128
    float* sA = sm + 128 * 128;     // 64 x 128
    const int t    = threadIdx.x;
    const int row0 = blockIdx.x * 64;
    const int c0   = blockIdx.y * 128;
    const int K    = (MODE == 2) ? 256 : 128;
    const int LDW  = (MODE == 0) ? 128 : 256;
    const int LDA  = (MODE == 2) ? 256 : 128;
    const int LDC  = (MODE == 0) ? 128 : 256;

    float acc[8][4];
#pragma unroll
    for (int j = 0; j < 8; j++)
#pragma unroll
        for (int q = 0; q < 4; q++) acc[j][q] = 0.f;

    for (int kc = 0; kc < K; kc += 128) {
#pragma unroll
        for (int i = 0; i < 16; i++) {            // W chunk
            int v = t + 256 * i;
            int kk = v >> 5, c4 = (v & 31) << 2;
            *(float4*)(sW + kk * 128 + c4) =
                *(const float4*)(W + (size_t)(kc + kk) * LDW + c0 + c4);
        }
#pragma unroll
        for (int i = 0; i < 8; i++) {             // A chunk
            int v = t + 256 * i;
            int r = v >> 5, k4 = (v & 31) << 2;
            int row = row0 + r;
            float4 a = make_float4(0.f, 0.f, 0.f, 0.f);
            if (row < N) {
                if (MODE == 1) {
                    float4 g = *(const float4*)(A1 + (size_t)row * 128 + k4);
                    float4 x = *(const float4*)(A0 + (size_t)row * 128 + k4);
                    float4 b = *(const float4*)(bin + k4);
                    a.x = __fadd_rn(fmaxf(__fadd_rn(g.x, b.x), 0.f), x.x);
                    a.y = __fadd_rn(fmaxf(__fadd_rn(g.y, b.y), 0.f), x.y);
                    a.z = __fadd_rn(fmaxf(__fadd_rn(g.z, b.z), 0.f), x.z);
                    a.w = __fadd_rn(fmaxf(__fadd_rn(g.w, b.w), 0.f), x.w);
                } else {
                    a = *(const float4*)(A0 + (size_t)row * LDA + kc + k4);
                }
            }
            *(float4*)(sA + r * 128 + k4) = a;
        }
        __syncthreads();

        const int cx = (t & 31) * 4;
        const int r0 = (t >> 5) * 8;
#pragma unroll 4
        for (int k = 0; k < 128; k++) {
            float4 w = *(const float4*)(sW + k * 128 + cx);
#pragma unroll
            for (int j = 0; j < 8; j++) {
                float a = sA[(r0 + j) * 128 + k];
                acc[j][0] = fmaf(a, w.x, acc[j][0]);
                acc[j][1] = fmaf(a, w.y, acc[j][1]);
                acc[j][2] = fmaf(a, w.z, acc[j][2]);
                acc[j][3] = fmaf(a, w.w, acc[j][3]);
            }
        }
        __syncthreads();
    }

    const int cx = (t & 31) * 4;
    const int r0 = (t >> 5) * 8;
    float4 b = make_float4(0.f, 0.f, 0.f, 0.f);
    if (MODE != 0) b = *(const float4*)(bout + c0 + cx);
#pragma unroll
    for (int j = 0; j < 8; j++) {
        int row = row0 + r0 + j;
        if (row >= N) continue;
        float4 o = make_float4(acc[j][0], acc[j][1], acc[j][2], acc[j][3]);
        if (MODE != 0) {
            o.x = __fadd_rn(o.x, b.x); o.x = (o.x >= 0.f) ? o.x : __fmul_rn(0.01f, o.x);
            o.y = __fadd_rn(o.y, b.y); o.y = (o.y >= 0.f) ? o.y : __fmul_rn(0.01f, o.y);
            o.z = __fadd_rn(o.z, b.z); o.z = (o.z >= 0.f) ? o.z : __fmul_rn(0.01f, o.z);
            o.w = __fadd_rn(o.w, b.w); o.w = (o.w >= 0.f) ? o.w : __fmul_rn(0.01f, o.w);
        }
        *(float4*)(Cout + (size_t)row * LDC + c0 + cx) = o;
    }
}

// conc = softplus(h2 @ W3 + b3) + 1e-20   (warp per row)
__global__ void k_conc(const float* __restrict__ W3, const float* __restrict__ b3, int N) {
    int row = blockIdx.x * 8 + (threadIdx.x >> 5);
    if (row >= N) return;
    int lane = threadIdx.x & 31;
    const float4* hr = (const float4*)(g_h2 + (size_t)row * 256);
    const float4* w4 = (const float4*)W3;
    float s = 0.f;
#pragma unroll
    for (int j = lane; j < 64; j += 32) {
        float4 a = hr[j], w = w4[j];
        s = fmaf(a.x, w.x, s); s = fmaf(a.y, w.y, s);
        s = fmaf(a.z, w.z, s); s = fmaf(a.w, w.w, s);
    }
#pragma unroll
    for (int o = 16; o; o >>= 1) s += __shfl_xor_sync(0xFFFFFFFFu, s, o);
    if (lane == 0) {
        float z = __fadd_rn(s, b3[0]);
        double sp = fmax((double)z, 0.0) + log1p(exp(-fabs((double)z)));
        g_conc[row] = __fadd_rn((float)sp, 1e-20f);
    }
}

// ------------------------- loggamma sampler (jax _gamma_one) -----------------
__global__ void k_sample(int N) {
    int i = blockIdx.x * blockDim.x + threadIdx.x;
    if (i >= N) return;
    float alpha = g_conc[i];
    K2 key = split_big(K2{0u, 42u}, (unsigned)i, (unsigned)N);   // split(key(42), N)[i]

    bool boost = (alpha >= 1.0f);
    float alpha_b = boost ? alpha : __fadd_rn(alpha, 1.0f);
    const float third = 0.3333333433f;                            // f32(1/3)
    float d = __fsub_rn(alpha_b, third);
    float c = __fdiv_rn(third, __fsqrt_rn(d));

    K2 k0, sub;
    split2(key, k0, sub);
    key = k0;
    float u_boost = u01(sub);

    float V;
    for (;;) {
        K2 nk, xk, uk;
        split3(key, nk, xk, uk);
        key = nk;
        float x, v;
        K2 kk = xk;
        do {
            K2 a, b;
            split2(kk, a, b);
            kk = a;
            x = nrm(b);
            v = __fadd_rn(1.0f, __fmul_rn(c, x));
        } while (v <= 0.0f);
        float X = __fmul_rn(x, x);
        V = __fmul_rn(__fmul_rn(v, v), v);
        float U = u01(uk);
        // reject while (U >= 1-0.0331 X^2) && (log U >= X/2 + d(1-V+log V))
        float sq = __fsub_rn(1.0f, __fmul_rn(0.0331f, __fmul_rn(X, X)));
        if (U < sq) break;
        float logU = (float)log((double)U);
        float logV = (float)log((double)V);
        float rhs = __fadd_rn(__fmul_rn(X, 0.5f),
                              __fmul_rn(d, __fadd_rn(__fsub_rn(1.0f, V), logV)));
        if (logU < rhs) break;
    }
    float log_sample = __fadd_rn((float)log((double)d), (float)log((double)V));
    float lg;
    if (boost) lg = log_sample;
    else {
        float lb = __fmul_rn((float)log1p(-(double)u_boost), __fdiv_rn(1.0f, alpha));
        lg = __fadd_rn(log_sample, lb);
    }
    g_lg[i] = lg;
}

// ------------------------- per-row finish: softmax + log_prob ----------------
__global__ void k_row(float* __restrict__ out, int N, int writeLP) {
    int b = blockIdx.x;
    int t = threadIdx.x;
    __shared__ float  rf[256];
    __shared__ double rd[256];
    const float* lg = g_lg   + (size_t)b * ADIM;
    const float* cc = g_conc + (size_t)b * ADIM;

    float m = -1e30f;
    for (int j = t; j < ADIM; j += 256) m = fmaxf(m, lg[j]);
    rf[t] = m; __syncthreads();
    for (int s = 128; s; s >>= 1) { if (t < s) rf[t] = fmaxf(rf[t], rf[t + s]); __syncthreads(); }
    m = rf[0]; __syncthreads();

    float se = 0.f;
    for (int j = t; j < ADIM; j += 256)
        se = __fadd_rn(se, (float)exp((double)__fsub_rn(lg[j], m)));
    rf[t] = se; __syncthreads();
    for (int s = 128; s; s >>= 1) { if (t < s) rf[t] = __fadd_rn(rf[t], rf[t + s]); __syncthreads(); }
    float lse = __fadd_rn((float)log((double)rf[0]), m);
    __syncthreads();

    double t1 = 0.0, t3 = 0.0, sc = 0.0;
    for (int j = t; j < ADIM; j += 256) {
        float af = (float)exp((double)__fsub_rn(lg[j], lse));
        out[(size_t)b * ADIM + j] = af;
        float cj = cc[j];
        t1 += (double)__fsub_rn(cj, 1.0f) * log((double)af);
        t3 += (double)lgammaf(cj);
        sc += (double)cj;
    }
    rd[t] = t1; __syncthreads();
    for (int s = 128; s; s >>= 1) { if (t < s) rd[t] += rd[t + s]; __syncthreads(); }
    t1 = rd[0]; __syncthreads();
    rd[t] = t3; __syncthreads();
    for (int s = 128; s; s >>= 1) { if (t < s) rd[t] += rd[t + s]; __syncthreads(); }
    t3 = rd[0]; __syncthreads();
    rd[t] = sc; __syncthreads();
    for (int s = 128; s; s >>= 1) { if (t < s) rd[t] += rd[t + s]; __syncthreads(); }
    sc = rd[0];

    if (t == 0 && writeLP) {
        float scf = (float)sc;                        // reference sums conc in f32
        double lp = t1 + lgamma((double)scf) - t3;
        out[(size_t)N + b] = (float)lp;
    }
}

// ------------------------- launch -------------------------------------------
extern "C" void kernel_launch(void* const* d_in, const int* in_sizes, int n_in,
                              void* d_out, int out_size) {
    const float* x      = (const float*)d_in[0];
    const float* W_conv = (const float*)d_in[1];
    const float* b_conv = (const float*)d_in[2];
    const float* W1     = (const float*)d_in[3];
    const float* b1     = (const float*)d_in[4];
    const float* W2     = (const float*)d_in[5];
    const float* b2     = (const float*)d_in[6];
    const float* W3     = (const float*)d_in[7];
    const float* b3     = (const float*)d_in[8];
    const int*   ei     = (const int*)d_in[9];
    float* out = (float*)d_out;

    int N = in_sizes[0] / 128;
    int E = in_sizes[9] / 2;
    int B = N / ADIM;
    const int* src = ei;
    const int* dst = ei + E;

    const int SMEM = (128 * 128 + 64 * 128) * 4;   // 98304
    cudaFuncSetAttribute(k_gemm<0>, cudaFuncAttributeMaxDynamicSharedMemorySize, SMEM);
    cudaFuncSetAttribute(k_gemm<1>, cudaFuncAttributeMaxDynamicSharedMemorySize, SMEM);
    cudaFuncSetAttribute(k_gemm<2>, cudaFuncAttributeMaxDynamicSharedMemorySize, SMEM);

    k_deg_init<<<(N + 255) / 256, 256>>>(N);
    k_deg_count<<<(E + 255) / 256, 256>>>(dst, E);
    k_dinv<<<(N + 255) / 256, 256>>>(N);

    float* gh = nullptr; float* gagg = nullptr; float* gh1 = nullptr; float* gh2 = nullptr;
    cudaGetSymbolAddress((void**)&gh,  g_h);
    cudaGetSymbolAddress((void**)&gagg, g_agg);
    cudaGetSymbolAddress((void**)&gh1, g_h1);
    cudaGetSymbolAddress((void**)&gh2, g_h2);

    dim3 g0((N + 63) / 64, 1), g1((N + 63) / 64, 2);
    k_gemm<0><<<g0, 256, SMEM>>>(x, nullptr, nullptr, W_conv, nullptr, gh, N);
    k_self<<<(N * 32 + 255) / 256, 256>>>(N * 32);
    k_scatter<<<(E + 7) / 8, 256>>>(src, dst, E);
    k_gemm<1><<<g1, 256, SMEM>>>(x, gagg, b_conv, W1, b1, gh1, N);
    k_gemm<2><<<g1, 256, SMEM>>>(gh1, nullptr, nullptr, W2, b2, gh2, N);
    k_conc<<<(N + 7) / 8, 256>>>(W3, b3, N);
    k_sample<<<(N + 127) / 128, 128>>>(N);
    int writeLP = (out_size >= N + B) ? 1 : 0;
    k_row<<<B, 256>>>(out, N, writeLP);
}

// round 3
// speedup vs baseline: 1.1459x; 1.1459x over previous
#include <cuda_runtime.h>
#include <math.h>
#include <stdint.h>

#define NN_MAX 100000
#define ADIM   1000

// ------------------------- scratch (no runtime alloc) -----------------------
__device__ float g_h   [(size_t)NN_MAX*128];
__device__ float g_agg [(size_t)NN_MAX*128];
__device__ float g_h1  [(size_t)NN_MAX*256];
__device__ float g_h2  [(size_t)NN_MAX*256];
__device__ float g_deg [NN_MAX];
__device__ float g_dinv[NN_MAX];
__device__ float g_conc[NN_MAX];
__device__ float g_lg  [NN_MAX];

// ------------------------- threefry2x32 (JAX-exact) -------------------------
struct K2 { unsigned a, b; };

__device__ __forceinline__ void tf_round(unsigned &x0, unsigned &x1, int r) {
    x0 += x1;
    x1 = (x1 << r) | (x1 >> (32 - r));
    x1 ^= x0;
}
__device__ __forceinline__ K2 tf_block(unsigned k0, unsigned k1, unsigned x0, unsigned x1) {
    unsigned k2 = k0 ^ k1 ^ 0x1BD11BDAu;
    x0 += k0; x1 += k1;
    tf_round(x0,x1,13); tf_round(x0,x1,15); tf_round(x0,x1,26); tf_round(x0,x1,6);
    x0 += k1; x1 += k2 + 1u;
    tf_round(x0,x1,17); tf_round(x0,x1,29); tf_round(x0,x1,16); tf_round(x0,x1,24);
    x0 += k2; x1 += k0 + 2u;
    tf_round(x0,x1,13); tf_round(x0,x1,15); tf_round(x0,x1,26); tf_round(x0,x1,6);
    x0 += k0; x1 += k1 + 3u;
    tf_round(x0,x1,17); tf_round(x0,x1,29); tf_round(x0,x1,16); tf_round(x0,x1,24);
    x0 += k1; x1 += k2 + 4u;
    tf_round(x0,x1,13); tf_round(x0,x1,15); tf_round(x0,x1,26); tf_round(x0,x1,6);
    x0 += k2; x1 += k0 + 5u;
    K2 r; r.a = x0; r.b = x1; return r;
}

// partitionable ("foldlike") stream layout
__device__ __forceinline__ unsigned rbits(K2 k) {
    K2 r = tf_block(k.a, k.b, 0u, 0u);
    return r.a ^ r.b;
}
__device__ __forceinline__ void split2(K2 k, K2 &o0, K2 &o1) {
    o0 = tf_block(k.a, k.b, 0u, 0u);
    o1 = tf_block(k.a, k.b, 0u, 1u);
}
__device__ __forceinline__ void split3(K2 k, K2 &o0, K2 &o1, K2 &o2) {
    o0 = tf_block(k.a, k.b, 0u, 0u);
    o1 = tf_block(k.a, k.b, 0u, 1u);
    o2 = tf_block(k.a, k.b, 0u, 2u);
}
__device__ __forceinline__ K2 split_big(K2 k, unsigned i) {
    return tf_block(k.a, k.b, 0u, i);
}

__device__ __forceinline__ float u01(K2 k) {
    unsigned bits = rbits(k);
    return __uint_as_float((bits >> 9) | 0x3f800000u) - 1.0f;   // [0,1)
}

// XLA ErfInv32 polynomial
__device__ __forceinline__ float erfinv_xla(float x) {
    float xx = __fmul_rn(x, x);
    float w = (float)(-log1p(-(double)xx));
    float p;
    if (w < 5.0f) {
        w = __fsub_rn(w, 2.5f);
        p = 2.81022636e-08f;
        p = fmaf(p, w, 3.43273939e-07f);
        p = fmaf(p, w, -3.5233877e-06f);
        p = fmaf(p, w, -4.39150654e-06f);
        p = fmaf(p, w, 0.00021858087f);
        p = fmaf(p, w, -0.00125372503f);
        p = fmaf(p, w, -0.00417768164f);
        p = fmaf(p, w, 0.246640727f);
        p = fmaf(p, w, 1.50140941f);
    } else {
        w = __fsub_rn(__fsqrt_rn(w), 3.0f);
        p = -0.000200214257f;
        p = fmaf(p, w, 0.000100950558f);
        p = fmaf(p, w, 0.00134934322f);
        p = fmaf(p, w, -0.00367342844f);
        p = fmaf(p, w, 0.00573950773f);
        p = fmaf(p, w, -0.0076224613f);
        p = fmaf(p, w, 0.00943887047f);
        p = fmaf(p, w, 1.00167406f);
        p = fmaf(p, w, 2.83297682f);
    }
    return __fmul_rn(p, x);
}

// jax.random.normal scalar
__device__ __forceinline__ float nrm(K2 k) {
    float f = u01(k);
    const float lo = __uint_as_float(0xBF7FFFFFu);
    float v = __fadd_rn(__fmul_rn(f, 2.0f), lo);
    v = fmaxf(lo, v);
    return __fmul_rn(__uint_as_float(0x3FB504F3u), erfinv_xla(v));
}

// ------------------------- degree / norm ------------------------------------
__global__ void k_deg_init(int n) {
    int i = blockIdx.x * blockDim.x + threadIdx.x;
    if (i < n) g_deg[i] = 1.0f;
}
__global__ void k_deg_count(const int* __restrict__ dst, int E) {
    int e = blockIdx.x * blockDim.x + threadIdx.x;
    if (e < E) atomicAdd(&g_deg[dst[e]], 1.0f);
}
__global__ void k_dinv(int n) {
    int i = blockIdx.x * blockDim.x + threadIdx.x;
    if (i < n) g_dinv[i] = (float)(1.0 / sqrt((double)g_deg[i]));
}

// self-loop init: agg[i] = h[i] * dinv[i]^2
__global__ void k_self(int n4) {
    int idx = blockIdx.x * blockDim.x + threadIdx.x;
    if (idx >= n4) return;
    int node = idx >> 5;
    float di = g_dinv[node];
    float n2 = __fmul_rn(di, di);
    float4 v = ((const float4*)g_h)[idx];
    float4 o;
    o.x = __fmul_rn(v.x, n2); o.y = __fmul_rn(v.y, n2);
    o.z = __fmul_rn(v.z, n2); o.w = __fmul_rn(v.w, n2);
    ((float4*)g_agg)[idx] = o;
}

// edge scatter: one warp per edge, vector red.global.add.v4.f32
__global__ void k_scatter(const int* __restrict__ src, const int* __restrict__ dst, int E) {
    int e = blockIdx.x * 8 + (threadIdx.x >> 5);
    if (e >= E) return;
    int lane = threadIdx.x & 31;
    int s = __ldg(&src[e]);
    int d = __ldg(&dst[e]);
    float norm = __fmul_rn(g_dinv[s], g_dinv[d]);
    float4 v = *(const float4*)(g_h + (size_t)s * 128 + lane * 4);
    float* out = g_agg + (size_t)d * 128 + lane * 4;
    float m0 = __fmul_rn(v.x, norm);
    float m1 = __fmul_rn(v.y, norm);
    float m2 = __fmul_rn(v.z, norm);
    float m3 = __fmul_rn(v.w, norm);
    asm volatile("red.global.add.v4.f32 [%0], {%1,%2,%3,%4};"
                 :: "l"(out), "f"(m0), "f"(m1), "f"(m2), "f"(m3) : "memory");
}

// ------------------------- GEMMs: 64x128 tile, 128 thr, 8x8 reg tile ---------
// MODE 0: g_h  = x @ Wc                               (K=128, LDC=128)
// MODE 1: g_h1 = leaky((relu(agg+bc)+x) @ W1 + b1)    (K=128, LDC=256)
// MODE 2: g_h2 = leaky(h1 @ W2 + b2)                  (K=256, LDC=256)
template<int MODE>
__global__ void __launch_bounds__(128) k_gemm(const float* __restrict__ A0,
                                              const float* __restrict__ A1,
                                              const float* __restrict__ bin,
                                              const float* __restrict__ W,
                                              const float* __restrict__ bout,
                                              float* __restrict__ Cout, int N) {
    extern __shared__ float sm[];
    float* sW = sm;               // 128 x 128
    float* sA = sm + 128 * 128;   // 64 x 128
    const int t    = threadIdx.x;
    const int row0 = blockIdx.x * 64;
    const int c0   = blockIdx.y * 128;
    const int K    = (MODE == 2) ? 256 : 128;
    const int LDW  = (MODE == 0) ? 128 : 256;
    const int LDA  = (MODE == 2) ? 256 : 128;
    const int LDC  = (MODE == 0) ? 128 : 256;

    const int tx = t & 15;        // 16 col-groups
    const int ty = t >> 4;        // 8 row-groups
    const int cx = tx * 4;        // cols cx..cx+3 and cx+64..cx+67
    const int r0 = ty * 8;

    float acc[8][8];
#pragma unroll
    for (int j = 0; j < 8; j++)
#pragma unroll
        for (int q = 0; q < 8; q++) acc[j][q] = 0.f;

    for (int kc = 0; kc < K; kc += 128) {
#pragma unroll
        for (int i = 0; i < 32; i++) {            // W tile: 4096 float4
            int v  = t + 128 * i;
            int kk = v >> 5, c4 = (v & 31) << 2;
            *(float4*)(sW + kk * 128 + c4) =
                *(const float4*)(W + (size_t)(kc + kk) * LDW + c0 + c4);
        }
#pragma unroll
        for (int i = 0; i < 16; i++) {            // A tile: 2048 float4
            int v  = t + 128 * i;
            int r  = v >> 5, k4 = (v & 31) << 2;
            int row = row0 + r;
            float4 a = make_float4(0.f, 0.f, 0.f, 0.f);
            if (row < N) {
                if (MODE == 1) {
                    float4 g = *(const float4*)(A1 + (size_t)row * 128 + k4);
                    float4 x = *(const float4*)(A0 + (size_t)row * 128 + k4);
                    float4 b = *(const float4*)(bin + k4);
                    a.x = __fadd_rn(fmaxf(__fadd_rn(g.x, b.x), 0.f), x.x);
                    a.y = __fadd_rn(fmaxf(__fadd_rn(g.y, b.y), 0.f), x.y);
                    a.z = __fadd_rn(fmaxf(__fadd_rn(g.z, b.z), 0.f), x.z);
                    a.w = __fadd_rn(fmaxf(__fadd_rn(g.w, b.w), 0.f), x.w);
                } else {
                    a = *(const float4*)(A0 + (size_t)row * LDA + kc + k4);
                }
            }
            *(float4*)(sA + r * 128 + k4) = a;
        }
        __syncthreads();

#pragma unroll 2
        for (int k = 0; k < 128; k += 4) {
            float4 a[8];
#pragma unroll
            for (int j = 0; j < 8; j++)
                a[j] = *(const float4*)(sA + (r0 + j) * 128 + k);
#pragma unroll
            for (int kk = 0; kk < 4; kk++) {
                float4 w0 = *(const float4*)(sW + (k + kk) * 128 + cx);
                float4 w1 = *(const float4*)(sW + (k + kk) * 128 + cx + 64);
#pragma unroll
                for (int j = 0; j < 8; j++) {
                    float av = (kk == 0) ? a[j].x : (kk == 1) ? a[j].y :
                               (kk == 2) ? a[j].z : a[j].w;
                    acc[j][0] = fmaf(av, w0.x, acc[j][0]);
                    acc[j][1] = fmaf(av, w0.y, acc[j][1]);
                    acc[j][2] = fmaf(av, w0.z, acc[j][2]);
                    acc[j][3] = fmaf(av, w0.w, acc[j][3]);
                    acc[j][4] = fmaf(av, w1.x, acc[j][4]);
                    acc[j][5] = fmaf(av, w1.y, acc[j][5]);
                    acc[j][6] = fmaf(av, w1.z, acc[j][6]);
                    acc[j][7] = fmaf(av, w1.w, acc[j][7]);
                }
            }
        }
        __syncthreads();
    }

    float4 b0 = make_float4(0.f, 0.f, 0.f, 0.f);
    float4 b1v = b0;
    if (MODE != 0) {
        b0  = *(const float4*)(bout + c0 + cx);
        b1v = *(const float4*)(bout + c0 + cx + 64);
    }
#pragma unroll
    for (int j = 0; j < 8; j++) {
        int row = row0 + r0 + j;
        if (row >= N) continue;
        float4 o0 = make_float4(acc[j][0], acc[j][1], acc[j][2], acc[j][3]);
        float4 o1 = make_float4(acc[j][4], acc[j][5], acc[j][6], acc[j][7]);
        if (MODE != 0) {
            o0.x = __fadd_rn(o0.x, b0.x);  o0.x = (o0.x >= 0.f) ? o0.x : __fmul_rn(0.01f, o0.x);
            o0.y = __fadd_rn(o0.y, b0.y);  o0.y = (o0.y >= 0.f) ? o0.y : __fmul_rn(0.01f, o0.y);
            o0.z = __fadd_rn(o0.z, b0.z);  o0.z = (o0.z >= 0.f) ? o0.z : __fmul_rn(0.01f, o0.z);
            o0.w = __fadd_rn(o0.w, b0.w);  o0.w = (o0.w >= 0.f) ? o0.w : __fmul_rn(0.01f, o0.w);
            o1.x = __fadd_rn(o1.x, b1v.x); o1.x = (o1.x >= 0.f) ? o1.x : __fmul_rn(0.01f, o1.x);
            o1.y = __fadd_rn(o1.y, b1v.y); o1.y = (o1.y >= 0.f) ? o1.y : __fmul_rn(0.01f, o1.y);
            o1.z = __fadd_rn(o1.z, b1v.z); o1.z = (o1.z >= 0.f) ? o1.z : __fmul_rn(0.01f, o1.z);
            o1.w = __fadd_rn(o1.w, b1v.w); o1.w = (o1.w >= 0.f) ? o1.w : __fmul_rn(0.01f, o1.w);
        }
        *(float4*)(Cout + (size_t)row * LDC + c0 + cx)      = o0;
        *(float4*)(Cout + (size_t)row * LDC + c0 + cx + 64) = o1;
    }
}

// conc = softplus(h2 @ W3 + b3) + 1e-20   (warp per row)
__global__ void k_conc(const float* __restrict__ W3, const float* __restrict__ b3, int N) {
    int row = blockIdx.x * 8 + (threadIdx.x >> 5);
    if (row >= N) return;
    int lane = threadIdx.x & 31;
    const float4* hr = (const float4*)(g_h2 + (size_t)row * 256);
    const float4* w4 = (const float4*)W3;
    float s = 0.f;
#pragma unroll
    for (int j = lane; j < 64; j += 32) {
        float4 a = hr[j], w = w4[j];
        s = fmaf(a.x, w.x, s); s = fmaf(a.y, w.y, s);
        s = fmaf(a.z, w.z, s); s = fmaf(a.w, w.w, s);
    }
#pragma unroll
    for (int o = 16; o; o >>= 1) s += __shfl_xor_sync(0xFFFFFFFFu, s, o);
    if (lane == 0) {
        float z = __fadd_rn(s, b3[0]);
        double sp = fmax((double)z, 0.0) + log1p(exp(-fabs((double)z)));
        g_conc[row] = __fadd_rn((float)sp, 1e-20f);
    }
}

// ------------------------- loggamma sampler (jax _gamma_one) -----------------
__global__ void k_sample(int N) {
    int i = blockIdx.x * blockDim.x + threadIdx.x;
    if (i >= N) return;
    float alpha = g_conc[i];
    K2 key = split_big(K2{0u, 42u}, (unsigned)i);

    bool boost = (alpha >= 1.0f);
    float alpha_b = boost ? alpha : __fadd_rn(alpha, 1.0f);
    const float third = 0.3333333433f;
    float d = __fsub_rn(alpha_b, third);
    float c = __fdiv_rn(third, __fsqrt_rn(d));

    K2 k0, sub;
    split2(key, k0, sub);
    key = k0;
    float u_boost = u01(sub);

    float V;
    for (;;) {
        K2 nk, xk, uk;
        split3(key, nk, xk, uk);
        key = nk;
        float x, v;
        K2 kk = xk;
        do {
            K2 a, b;
            split2(kk, a, b);
            kk = a;
            x = nrm(b);
            v = __fadd_rn(1.0f, __fmul_rn(c, x));
        } while (v <= 0.0f);
        float X = __fmul_rn(x, x);
        V = __fmul_rn(__fmul_rn(v, v), v);
        float U = u01(uk);
        float sq = __fsub_rn(1.0f, __fmul_rn(0.0331f, __fmul_rn(X, X)));
        if (U < sq) break;
        float logU = (float)log((double)U);
        float logV = (float)log((double)V);
        float rhs = __fadd_rn(__fmul_rn(X, 0.5f),
                              __fmul_rn(d, __fadd_rn(__fsub_rn(1.0f, V), logV)));
        if (logU < rhs) break;
    }
    float log_sample = __fadd_rn((float)log((double)d), (float)log((double)V));
    float lg;
    if (boost) lg = log_sample;
    else {
        float lb = __fmul_rn((float)log1p(-(double)u_boost), __fdiv_rn(1.0f, alpha));
        lg = __fadd_rn(log_sample, lb);
    }
    g_lg[i] = lg;
}

// ------------------------- per-row finish: softmax + log_prob ----------------
__global__ void k_row(float* __restrict__ out, int N, int writeLP) {
    int b = blockIdx.x;
    int t = threadIdx.x;
    __shared__ float  rf[256];
    __shared__ double rd[256];
    const float* lg = g_lg   + (size_t)b * ADIM;
    const float* cc = g_conc + (size_t)b * ADIM;

    float m = -1e30f;
    for (int j = t; j < ADIM; j += 256) m = fmaxf(m, lg[j]);
    rf[t] = m; __syncthreads();
    for (int s = 128; s; s >>= 1) { if (t < s) rf[t] = fmaxf(rf[t], rf[t + s]); __syncthreads(); }
    m = rf[0]; __syncthreads();

    float se = 0.f;
    for (int j = t; j < ADIM; j += 256)
        se = __fadd_rn(se, (float)exp((double)__fsub_rn(lg[j], m)));
    rf[t] = se; __syncthreads();
    for (int s = 128; s; s >>= 1) { if (t < s) rf[t] = __fadd_rn(rf[t], rf[t + s]); __syncthreads(); }
    float lse = __fadd_rn((float)log((double)rf[0]), m);
    __syncthreads();

    double t1 = 0.0, t3 = 0.0, sc = 0.0;
    for (int j = t; j < ADIM; j += 256) {
        float af = (float)exp((double)__fsub_rn(lg[j], lse));
        out[(size_t)b * ADIM + j] = af;
        float cj = cc[j];
        t1 += (double)__fsub_rn(cj, 1.0f) * log((double)af);
        t3 += (double)lgammaf(cj);
        sc += (double)cj;
    }
    rd[t] = t1; __syncthreads();
    for (int s = 128; s; s >>= 1) { if (t < s) rd[t] += rd[t + s]; __syncthreads(); }
    t1 = rd[0]; __syncthreads();
    rd[t] = t3; __syncthreads();
    for (int s = 128; s; s >>= 1) { if (t < s) rd[t] += rd[t + s]; __syncthreads(); }
    t3 = rd[0]; __syncthreads();
    rd[t] = sc; __syncthreads();
    for (int s = 128; s; s >>= 1) { if (t < s) rd[t] += rd[t + s]; __syncthreads(); }
    sc = rd[0];

    if (t == 0 && writeLP) {
        float scf = (float)sc;
        double lp = t1 + lgamma((double)scf) - t3;
        out[(size_t)N + b] = (float)lp;
    }
}

// ------------------------- launch -------------------------------------------
extern "C" void kernel_launch(void* const* d_in, const int* in_sizes, int n_in,
                              void* d_out, int out_size) {
    const float* x      = (const float*)d_in[0];
    const float* W_conv = (const float*)d_in[1];
    const float* b_conv = (const float*)d_in[2];
    const float* W1     = (const float*)d_in[3];
    const float* b1     = (const float*)d_in[4];
    const float* W2     = (const float*)d_in[5];
    const float* b2     = (const float*)d_in[6];
    const float* W3     = (const float*)d_in[7];
    const float* b3     = (const float*)d_in[8];
    const int*   ei     = (const int*)d_in[9];
    float* out = (float*)d_out;

    int N = in_sizes[0] / 128;
    int E = in_sizes[9] / 2;
    int B = N / ADIM;
    const int* src = ei;
    const int* dst = ei + E;

    const int SMEM = (128 * 128 + 64 * 128) * 4;   // 98304
    cudaFuncSetAttribute(k_gemm<0>, cudaFuncAttributeMaxDynamicSharedMemorySize, SMEM);
    cudaFuncSetAttribute(k_gemm<1>, cudaFuncAttributeMaxDynamicSharedMemorySize, SMEM);
    cudaFuncSetAttribute(k_gemm<2>, cudaFuncAttributeMaxDynamicSharedMemorySize, SMEM);

    k_deg_init<<<(N + 255) / 256, 256>>>(N);
    k_deg_count<<<(E + 255) / 256, 256>>>(dst, E);
    k_dinv<<<(N + 255) / 256, 256>>>(N);

    float* gh = nullptr; float* gagg = nullptr; float* gh1 = nullptr; float* gh2 = nullptr;
    cudaGetSymbolAddress((void**)&gh,  g_h);
    cudaGetSymbolAddress((void**)&gagg, g_agg);
    cudaGetSymbolAddress((void**)&gh1, g_h1);
    cudaGetSymbolAddress((void**)&gh2, g_h2);

    dim3 g0((N + 63) / 64, 1), g1((N + 63) / 64, 2);
    k_gemm<0><<<g0, 128, SMEM>>>(x, nullptr, nullptr, W_conv, nullptr, gh, N);
    k_self<<<(N * 32 + 255) / 256, 256>>>(N * 32);
    k_scatter<<<(E + 7) / 8, 256>>>(src, dst, E);
    k_gemm<1><<<g1, 128, SMEM>>>(x, gagg, b_conv, W1, b1, gh1, N);
    k_gemm<2><<<g1, 128, SMEM>>>(gh1, nullptr, nullptr, W2, b2, gh2, N);
    k_conc<<<(N + 7) / 8, 256>>>(W3, b3, N);
    k_sample<<<(N + 127) / 128, 128>>>(N);
    int writeLP = (out_size >= N + B) ? 1 : 0;
    k_row<<<B, 256>>>(out, N, writeLP);
}

// round 4
// speedup vs baseline: 1.2748x; 1.1124x over previous
#include <cuda_runtime.h>
#include <math.h>
#include <stdint.h>

#define NN_MAX 100000
#define ADIM   1000

// ------------------------- scratch (no runtime alloc) -----------------------
__device__ float g_h   [(size_t)NN_MAX*128];
__device__ float g_agg [(size_t)NN_MAX*128];
__device__ float g_h1  [(size_t)NN_MAX*256];
__device__ float g_h2  [(size_t)NN_MAX*256];
__device__ float g_deg [NN_MAX];
__device__ float g_dinv[NN_MAX];
__device__ float g_conc[NN_MAX];
__device__ float g_lg  [NN_MAX];

// ------------------------- threefry2x32 (JAX-exact) -------------------------
struct K2 { unsigned a, b; };

__device__ __forceinline__ void tf_round(unsigned &x0, unsigned &x1, int r) {
    x0 += x1;
    x1 = (x1 << r) | (x1 >> (32 - r));
    x1 ^= x0;
}
__device__ __forceinline__ K2 tf_block(unsigned k0, unsigned k1, unsigned x0, unsigned x1) {
    unsigned k2 = k0 ^ k1 ^ 0x1BD11BDAu;
    x0 += k0; x1 += k1;
    tf_round(x0,x1,13); tf_round(x0,x1,15); tf_round(x0,x1,26); tf_round(x0,x1,6);
    x0 += k1; x1 += k2 + 1u;
    tf_round(x0,x1,17); tf_round(x0,x1,29); tf_round(x0,x1,16); tf_round(x0,x1,24);
    x0 += k2; x1 += k0 + 2u;
    tf_round(x0,x1,13); tf_round(x0,x1,15); tf_round(x0,x1,26); tf_round(x0,x1,6);
    x0 += k0; x1 += k1 + 3u;
    tf_round(x0,x1,17); tf_round(x0,x1,29); tf_round(x0,x1,16); tf_round(x0,x1,24);
    x0 += k1; x1 += k2 + 4u;
    tf_round(x0,x1,13); tf_round(x0,x1,15); tf_round(x0,x1,26); tf_round(x0,x1,6);
    x0 += k2; x1 += k0 + 5u;
    K2 r; r.a = x0; r.b = x1; return r;
}

// partitionable ("foldlike") stream layout
__device__ __forceinline__ unsigned rbits(K2 k) {
    K2 r = tf_block(k.a, k.b, 0u, 0u);
    return r.a ^ r.b;
}
__device__ __forceinline__ void split2(K2 k, K2 &o0, K2 &o1) {
    o0 = tf_block(k.a, k.b, 0u, 0u);
    o1 = tf_block(k.a, k.b, 0u, 1u);
}
__device__ __forceinline__ void split3(K2 k, K2 &o0, K2 &o1, K2 &o2) {
    o0 = tf_block(k.a, k.b, 0u, 0u);
    o1 = tf_block(k.a, k.b, 0u, 1u);
    o2 = tf_block(k.a, k.b, 0u, 2u);
}
__device__ __forceinline__ K2 split_big(K2 k, unsigned i) {
    return tf_block(k.a, k.b, 0u, i);
}

__device__ __forceinline__ float u01(K2 k) {
    unsigned bits = rbits(k);
    return __uint_as_float((bits >> 9) | 0x3f800000u) - 1.0f;   // [0,1)
}

// XLA ErfInv32 polynomial
__device__ __forceinline__ float erfinv_xla(float x) {
    float xx = __fmul_rn(x, x);
    float w = (float)(-log1p(-(double)xx));
    float p;
    if (w < 5.0f) {
        w = __fsub_rn(w, 2.5f);
        p = 2.81022636e-08f;
        p = fmaf(p, w, 3.43273939e-07f);
        p = fmaf(p, w, -3.5233877e-06f);
        p = fmaf(p, w, -4.39150654e-06f);
        p = fmaf(p, w, 0.00021858087f);
        p = fmaf(p, w, -0.00125372503f);
        p = fmaf(p, w, -0.00417768164f);
        p = fmaf(p, w, 0.246640727f);
        p = fmaf(p, w, 1.50140941f);
    } else {
        w = __fsub_rn(__fsqrt_rn(w), 3.0f);
        p = -0.000200214257f;
        p = fmaf(p, w, 0.000100950558f);
        p = fmaf(p, w, 0.00134934322f);
        p = fmaf(p, w, -0.00367342844f);
        p = fmaf(p, w, 0.00573950773f);
        p = fmaf(p, w, -0.0076224613f);
        p = fmaf(p, w, 0.00943887047f);
        p = fmaf(p, w, 1.00167406f);
        p = fmaf(p, w, 2.83297682f);
    }
    return __fmul_rn(p, x);
}

// jax.random.normal scalar
__device__ __forceinline__ float nrm(K2 k) {
    float f = u01(k);
    const float lo = __uint_as_float(0xBF7FFFFFu);
    float v = __fadd_rn(__fmul_rn(f, 2.0f), lo);
    v = fmaxf(lo, v);
    return __fmul_rn(__uint_as_float(0x3FB504F3u), erfinv_xla(v));
}

// ------------------------- degree / norm ------------------------------------
__global__ void k_deg_init(int n) {
    int i = blockIdx.x * blockDim.x + threadIdx.x;
    if (i < n) g_deg[i] = 1.0f;
}
__global__ void k_deg_count(const int* __restrict__ dst, int E) {
    int e = blockIdx.x * blockDim.x + threadIdx.x;
    if (e < E) atomicAdd(&g_deg[dst[e]], 1.0f);
}
__global__ void k_dinv(int n) {
    int i = blockIdx.x * blockDim.x + threadIdx.x;
    if (i < n) g_dinv[i] = (float)(1.0 / sqrt((double)g_deg[i]));
}

// self-loop init: agg[i] = h[i] * dinv[i]^2
__global__ void k_self(int n4) {
    int idx = blockIdx.x * blockDim.x + threadIdx.x;
    if (idx >= n4) return;
    int node = idx >> 5;
    float di = g_dinv[node];
    float n2 = __fmul_rn(di, di);
    float4 v = ((const float4*)g_h)[idx];
    float4 o;
    o.x = __fmul_rn(v.x, n2); o.y = __fmul_rn(v.y, n2);
    o.z = __fmul_rn(v.z, n2); o.w = __fmul_rn(v.w, n2);
    ((float4*)g_agg)[idx] = o;
}

// edge scatter: one warp per edge, vector red.global.add.v4.f32
__global__ void k_scatter(const int* __restrict__ src, const int* __restrict__ dst, int E) {
    int e = blockIdx.x * 8 + (threadIdx.x >> 5);
    if (e >= E) return;
    int lane = threadIdx.x & 31;
    int s = __ldg(&src[e]);
    int d = __ldg(&dst[e]);
    float norm = __fmul_rn(g_dinv[s], g_dinv[d]);
    float4 v = *(const float4*)(g_h + (size_t)s * 128 + lane * 4);
    float* out = g_agg + (size_t)d * 128 + lane * 4;
    float m0 = __fmul_rn(v.x, norm);
    float m1 = __fmul_rn(v.y, norm);
    float m2 = __fmul_rn(v.z, norm);
    float m3 = __fmul_rn(v.w, norm);
    asm volatile("red.global.add.v4.f32 [%0], {%1,%2,%3,%4};"
                 :: "l"(out), "f"(m0), "f"(m1), "f"(m2), "f"(m3) : "memory");
}

// ------------------------- GEMMs: classic double-buffered SGEMM -------------
// 128x128 block tile, 256 threads, 8x8 per-thread tile, K-slice = 8.
// MODE 0: g_h  = x @ Wc                               (K=128, LDC=128)
// MODE 1: g_h1 = leaky((relu(agg+bc)+x) @ W1 + b1)    (K=128, LDC=256)
// MODE 2: g_h2 = leaky(h1 @ W2 + b2)                  (K=256, LDC=256)
#define KB   8
#define PA   132   // sA pitch (floats): float4-aligned, de-conflicts transposed stores

template<int MODE>
__global__ void __launch_bounds__(256) k_gemm(const float* __restrict__ A0,
                                              const float* __restrict__ A1,
                                              const float* __restrict__ bin,
                                              const float* __restrict__ W,
                                              const float* __restrict__ bout,
                                              float* __restrict__ Cout, int N) {
    __shared__ float sA[2][KB][PA];     // k-major, transposed A
    __shared__ float sW[2][KB][128];

    const int t    = threadIdx.x;
    const int row0 = blockIdx.x * 128;
    const int c0   = blockIdx.y * 128;
    const int K    = (MODE == 2) ? 256 : 128;
    const int LDW  = (MODE == 0) ? 128 : 256;
    const int LDA  = (MODE == 2) ? 256 : 128;
    const int LDC  = (MODE == 0) ? 128 : 256;
    const int S    = K / KB;

    // loader indices
    const int ar  = t >> 1;             // A row within tile (0..127)
    const int ak4 = (t & 1) * 4;        // A k-offset (0 or 4)
    const int wr  = t >> 5;             // W k-row (0..7)
    const int wc4 = (t & 31) * 4;       // W col (0..124)
    const int arow = row0 + ar;

    // compute indices
    const int tx = t & 15;
    const int ty = t >> 4;
    const int cx = tx * 8;
    const int r0 = ty * 8;

    float acc[8][8];
#pragma unroll
    for (int j = 0; j < 8; j++)
#pragma unroll
        for (int q = 0; q < 8; q++) acc[j][q] = 0.f;

    float4 va, vw;

    // --- global load of slice s into registers ---
    auto gload = [&](int s) {
        int kc = s * KB;
        va = make_float4(0.f, 0.f, 0.f, 0.f);
        if (arow < N) {
            if (MODE == 1) {
                float4 g = *(const float4*)(A1 + (size_t)arow * 128 + kc + ak4);
                float4 x = *(const float4*)(A0 + (size_t)arow * 128 + kc + ak4);
                float4 b = *(const float4*)(bin + kc + ak4);
                va.x = __fadd_rn(fmaxf(__fadd_rn(g.x, b.x), 0.f), x.x);
                va.y = __fadd_rn(fmaxf(__fadd_rn(g.y, b.y), 0.f), x.y);
                va.z = __fadd_rn(fmaxf(__fadd_rn(g.z, b.z), 0.f), x.z);
                va.w = __fadd_rn(fmaxf(__fadd_rn(g.w, b.w), 0.f), x.w);
            } else {
                va = *(const float4*)(A0 + (size_t)arow * LDA + kc + ak4);
            }
        }
        vw = *(const float4*)(W + (size_t)(kc + wr) * LDW + c0 + wc4);
    };
    // --- store registers into smem buffer b ---
    auto sstore = [&](int b) {
        sA[b][ak4 + 0][ar] = va.x;
        sA[b][ak4 + 1][ar] = va.y;
        sA[b][ak4 + 2][ar] = va.z;
        sA[b][ak4 + 3][ar] = va.w;
        *(float4*)&sW[b][wr][wc4] = vw;
    };

    gload(0);
    sstore(0);
    __syncthreads();

    for (int s = 0; s < S; s++) {
        int buf = s & 1;
        if (s + 1 < S) gload(s + 1);
#pragma unroll
        for (int k = 0; k < KB; k++) {
            float4 a0 = *(const float4*)&sA[buf][k][r0];
            float4 a1 = *(const float4*)&sA[buf][k][r0 + 4];
            float4 w0 = *(const float4*)&sW[buf][k][cx];
            float4 w1 = *(const float4*)&sW[buf][k][cx + 4];
            float av[8] = {a0.x, a0.y, a0.z, a0.w, a1.x, a1.y, a1.z, a1.w};
#pragma unroll
            for (int j = 0; j < 8; j++) {
                acc[j][0] = fmaf(av[j], w0.x, acc[j][0]);
                acc[j][1] = fmaf(av[j], w0.y, acc[j][1]);
                acc[j][2] = fmaf(av[j], w0.z, acc[j][2]);
                acc[j][3] = fmaf(av[j], w0.w, acc[j][3]);
                acc[j][4] = fmaf(av[j], w1.x, acc[j][4]);
                acc[j][5] = fmaf(av[j], w1.y, acc[j][5]);
                acc[j][6] = fmaf(av[j], w1.z, acc[j][6]);
                acc[j][7] = fmaf(av[j], w1.w, acc[j][7]);
            }
        }
        if (s + 1 < S) sstore(buf ^ 1);
        __syncthreads();
    }

    float4 b0 = make_float4(0.f, 0.f, 0.f, 0.f);
    float4 b1v = b0;
    if (MODE != 0) {
        b0  = *(const float4*)(bout + c0 + cx);
        b1v = *(const float4*)(bout + c0 + cx + 4);
    }
#pragma unroll
    for (int j = 0; j < 8; j++) {
        int row = row0 + r0 + j;
        if (row >= N) continue;
        float4 o0 = make_float4(acc[j][0], acc[j][1], acc[j][2], acc[j][3]);
        float4 o1 = make_float4(acc[j][4], acc[j][5], acc[j][6], acc[j][7]);
        if (MODE != 0) {
            o0.x = __fadd_rn(o0.x, b0.x);  o0.x = (o0.x >= 0.f) ? o0.x : __fmul_rn(0.01f, o0.x);
            o0.y = __fadd_rn(o0.y, b0.y);  o0.y = (o0.y >= 0.f) ? o0.y : __fmul_rn(0.01f, o0.y);
            o0.z = __fadd_rn(o0.z, b0.z);  o0.z = (o0.z >= 0.f) ? o0.z : __fmul_rn(0.01f, o0.z);
            o0.w = __fadd_rn(o0.w, b0.w);  o0.w = (o0.w >= 0.f) ? o0.w : __fmul_rn(0.01f, o0.w);
            o1.x = __fadd_rn(o1.x, b1v.x); o1.x = (o1.x >= 0.f) ? o1.x : __fmul_rn(0.01f, o1.x);
            o1.y = __fadd_rn(o1.y, b1v.y); o1.y = (o1.y >= 0.f) ? o1.y : __fmul_rn(0.01f, o1.y);
            o1.z = __fadd_rn(o1.z, b1v.z); o1.z = (o1.z >= 0.f) ? o1.z : __fmul_rn(0.01f, o1.z);
            o1.w = __fadd_rn(o1.w, b1v.w); o1.w = (o1.w >= 0.f) ? o1.w : __fmul_rn(0.01f, o1.w);
        }
        *(float4*)(Cout + (size_t)row * LDC + c0 + cx)     = o0;
        *(float4*)(Cout + (size_t)row * LDC + c0 + cx + 4) = o1;
    }
}

// conc = softplus(h2 @ W3 + b3) + 1e-20   (warp per row)
__global__ void k_conc(const float* __restrict__ W3, const float* __restrict__ b3, int N) {
    int row = blockIdx.x * 8 + (threadIdx.x >> 5);
    if (row >= N) return;
    int lane = threadIdx.x & 31;
    const float4* hr = (const float4*)(g_h2 + (size_t)row * 256);
    const float4* w4 = (const float4*)W3;
    float s = 0.f;
#pragma unroll
    for (int j = lane; j < 64; j += 32) {
        float4 a = hr[j], w = w4[j];
        s = fmaf(a.x, w.x, s); s = fmaf(a.y, w.y, s);
        s = fmaf(a.z, w.z, s); s = fmaf(a.w, w.w, s);
    }
#pragma unroll
    for (int o = 16; o; o >>= 1) s += __shfl_xor_sync(0xFFFFFFFFu, s, o);
    if (lane == 0) {
        float z = __fadd_rn(s, b3[0]);
        double sp = fmax((double)z, 0.0) + log1p(exp(-fabs((double)z)));
        g_conc[row] = __fadd_rn((float)sp, 1e-20f);
    }
}

// ------------------------- loggamma sampler (jax _gamma_one) -----------------
__global__ void k_sample(int N) {
    int i = blockIdx.x * blockDim.x + threadIdx.x;
    if (i >= N) return;
    float alpha = g_conc[i];
    K2 key = split_big(K2{0u, 42u}, (unsigned)i);

    bool boost = (alpha >= 1.0f);
    float alpha_b = boost ? alpha : __fadd_rn(alpha, 1.0f);
    const float third = 0.3333333433f;
    float d = __fsub_rn(alpha_b, third);
    float c = __fdiv_rn(third, __fsqrt_rn(d));

    K2 k0, sub;
    split2(key, k0, sub);
    key = k0;
    float u_boost = u01(sub);

    float V;
    for (;;) {
        K2 nk, xk, uk;
        split3(key, nk, xk, uk);
        key = nk;
        float x, v;
        K2 kk = xk;
        do {
            K2 a, b;
            split2(kk, a, b);
            kk = a;
            x = nrm(b);
            v = __fadd_rn(1.0f, __fmul_rn(c, x));
        } while (v <= 0.0f);
        float X = __fmul_rn(x, x);
        V = __fmul_rn(__fmul_rn(v, v), v);
        float U = u01(uk);
        float sq = __fsub_rn(1.0f, __fmul_rn(0.0331f, __fmul_rn(X, X)));
        if (U < sq) break;
        float logU = (float)log((double)U);
        float logV = (float)log((double)V);
        float rhs = __fadd_rn(__fmul_rn(X, 0.5f),
                              __fmul_rn(d, __fadd_rn(__fsub_rn(1.0f, V), logV)));
        if (logU < rhs) break;
    }
    float log_sample = __fadd_rn((float)log((double)d), (float)log((double)V));
    float lg;
    if (boost) lg = log_sample;
    else {
        float lb = __fmul_rn((float)log1p(-(double)u_boost), __fdiv_rn(1.0f, alpha));
        lg = __fadd_rn(log_sample, lb);
    }
    g_lg[i] = lg;
}

// ------------------------- per-row finish: softmax + log_prob ----------------
__global__ void k_row(float* __restrict__ out, int N, int writeLP) {
    int b = blockIdx.x;
    int t = threadIdx.x;
    __shared__ float  rf[256];
    __shared__ double rd[256];
    const float* lg = g_lg   + (size_t)b * ADIM;
    const float* cc = g_conc + (size_t)b * ADIM;

    float m = -1e30f;
    for (int j = t; j < ADIM; j += 256) m = fmaxf(m, lg[j]);
    rf[t] = m; __syncthreads();
    for (int s = 128; s; s >>= 1) { if (t < s) rf[t] = fmaxf(rf[t], rf[t + s]); __syncthreads(); }
    m = rf[0]; __syncthreads();

    float se = 0.f;
    for (int j = t; j < ADIM; j += 256)
        se = __fadd_rn(se, (float)exp((double)__fsub_rn(lg[j], m)));
    rf[t] = se; __syncthreads();
    for (int s = 128; s; s >>= 1) { if (t < s) rf[t] = __fadd_rn(rf[t], rf[t + s]); __syncthreads(); }
    float lse = __fadd_rn((float)log((double)rf[0]), m);
    __syncthreads();

    double t1 = 0.0, t3 = 0.0, sc = 0.0;
    for (int j = t; j < ADIM; j += 256) {
        float af = (float)exp((double)__fsub_rn(lg[j], lse));
        out[(size_t)b * ADIM + j] = af;
        float cj = cc[j];
        t1 += (double)__fsub_rn(cj, 1.0f) * log((double)af);
        t3 += (double)lgammaf(cj);
        sc += (double)cj;
    }
    rd[t] = t1; __syncthreads();
    for (int s = 128; s; s >>= 1) { if (t < s) rd[t] += rd[t + s]; __syncthreads(); }
    t1 = rd[0]; __syncthreads();
    rd[t] = t3; __syncthreads();
    for (int s = 128; s; s >>= 1) { if (t < s) rd[t] += rd[t + s]; __syncthreads(); }
    t3 = rd[0]; __syncthreads();
    rd[t] = sc; __syncthreads();
    for (int s = 128; s; s >>= 1) { if (t < s) rd[t] += rd[t + s]; __syncthreads(); }
    sc = rd[0];

    if (t == 0 && writeLP) {
        float scf = (float)sc;
        double lp = t1 + lgamma((double)scf) - t3;
        out[(size_t)N + b] = (float)lp;
    }
}

// ------------------------- launch -------------------------------------------
extern "C" void kernel_launch(void* const* d_in, const int* in_sizes, int n_in,
                              void* d_out, int out_size) {
    const float* x      = (const float*)d_in[0];
    const float* W_conv = (const float*)d_in[1];
    const float* b_conv = (const float*)d_in[2];
    const float* W1     = (const float*)d_in[3];
    const float* b1     = (const float*)d_in[4];
    const float* W2     = (const float*)d_in[5];
    const float* b2     = (const float*)d_in[6];
    const float* W3     = (const float*)d_in[7];
    const float* b3     = (const float*)d_in[8];
    const int*   ei     = (const int*)d_in[9];
    float* out = (float*)d_out;

    int N = in_sizes[0] / 128;
    int E = in_sizes[9] / 2;
    int B = N / ADIM;
    const int* src = ei;
    const int* dst = ei + E;

    k_deg_init<<<(N + 255) / 256, 256>>>(N);
    k_deg_count<<<(E + 255) / 256, 256>>>(dst, E);
    k_dinv<<<(N + 255) / 256, 256>>>(N);

    float* gh = nullptr; float* gagg = nullptr; float* gh1 = nullptr; float* gh2 = nullptr;
    cudaGetSymbolAddress((void**)&gh,  g_h);
    cudaGetSymbolAddress((void**)&gagg, g_agg);
    cudaGetSymbolAddress((void**)&gh1, g_h1);
    cudaGetSymbolAddress((void**)&gh2, g_h2);

    dim3 g0((N + 127) / 128, 1), g1((N + 127) / 128, 2);
    k_gemm<0><<<g0, 256>>>(x, nullptr, nullptr, W_conv, nullptr, gh, N);
    k_self<<<(N * 32 + 255) / 256, 256>>>(N * 32);
    k_scatter<<<(E + 7) / 8, 256>>>(src, dst, E);
    k_gemm<1><<<g1, 256>>>(x, gagg, b_conv, W1, b1, gh1, N);
    k_gemm<2><<<g1, 256>>>(gh1, nullptr, nullptr, W2, b2, gh2, N);
    k_conc<<<(N + 7) / 8, 256>>>(W3, b3, N);
    k_sample<<<(N + 127) / 128, 128>>>(N);
    int writeLP = (out_size >= N + B) ? 1 : 0;
    k_row<<<B, 256>>>(out, N, writeLP);
}

// round 5
// speedup vs baseline: 1.3737x; 1.0776x over previous
#include <cuda_runtime.h>
#include <math.h>
#include <stdint.h>

#define NN_MAX 100000
#define ADIM   1000

// ------------------------- scratch (no runtime alloc) -----------------------
__device__ float g_h   [(size_t)NN_MAX*128];
__device__ float g_agg [(size_t)NN_MAX*128];
__device__ float g_h1  [(size_t)NN_MAX*256];
__device__ float g_h2  [(size_t)NN_MAX*256];
__device__ float g_deg [NN_MAX];
__device__ float g_dinv[NN_MAX];
__device__ float g_conc[NN_MAX];
__device__ float g_lg  [NN_MAX];

// ------------------------- threefry2x32 (JAX-exact) -------------------------
struct K2 { unsigned a, b; };

__device__ __forceinline__ void tf_round(unsigned &x0, unsigned &x1, int r) {
    x0 += x1;
    x1 = (x1 << r) | (x1 >> (32 - r));
    x1 ^= x0;
}
__device__ __forceinline__ K2 tf_block(unsigned k0, unsigned k1, unsigned x0, unsigned x1) {
    unsigned k2 = k0 ^ k1 ^ 0x1BD11BDAu;
    x0 += k0; x1 += k1;
    tf_round(x0,x1,13); tf_round(x0,x1,15); tf_round(x0,x1,26); tf_round(x0,x1,6);
    x0 += k1; x1 += k2 + 1u;
    tf_round(x0,x1,17); tf_round(x0,x1,29); tf_round(x0,x1,16); tf_round(x0,x1,24);
    x0 += k2; x1 += k0 + 2u;
    tf_round(x0,x1,13); tf_round(x0,x1,15); tf_round(x0,x1,26); tf_round(x0,x1,6);
    x0 += k0; x1 += k1 + 3u;
    tf_round(x0,x1,17); tf_round(x0,x1,29); tf_round(x0,x1,16); tf_round(x0,x1,24);
    x0 += k1; x1 += k2 + 4u;
    tf_round(x0,x1,13); tf_round(x0,x1,15); tf_round(x0,x1,26); tf_round(x0,x1,6);
    x0 += k2; x1 += k0 + 5u;
    K2 r; r.a = x0; r.b = x1; return r;
}

// partitionable ("foldlike") stream layout
__device__ __forceinline__ unsigned rbits(K2 k) {
    K2 r = tf_block(k.a, k.b, 0u, 0u);
    return r.a ^ r.b;
}
__device__ __forceinline__ void split2(K2 k, K2 &o0, K2 &o1) {
    o0 = tf_block(k.a, k.b, 0u, 0u);
    o1 = tf_block(k.a, k.b, 0u, 1u);
}
__device__ __forceinline__ void split3(K2 k, K2 &o0, K2 &o1, K2 &o2) {
    o0 = tf_block(k.a, k.b, 0u, 0u);
    o1 = tf_block(k.a, k.b, 0u, 1u);
    o2 = tf_block(k.a, k.b, 0u, 2u);
}
__device__ __forceinline__ K2 split_big(K2 k, unsigned i) {
    return tf_block(k.a, k.b, 0u, i);
}

__device__ __forceinline__ float u01(K2 k) {
    unsigned bits = rbits(k);
    return __uint_as_float((bits >> 9) | 0x3f800000u) - 1.0f;   // [0,1)
}

// XLA ErfInv32 polynomial
__device__ __forceinline__ float erfinv_xla(float x) {
    float xx = __fmul_rn(x, x);
    float w = (float)(-log1p(-(double)xx));
    float p;
    if (w < 5.0f) {
        w = __fsub_rn(w, 2.5f);
        p = 2.81022636e-08f;
        p = fmaf(p, w, 3.43273939e-07f);
        p = fmaf(p, w, -3.5233877e-06f);
        p = fmaf(p, w, -4.39150654e-06f);
        p = fmaf(p, w, 0.00021858087f);
        p = fmaf(p, w, -0.00125372503f);
        p = fmaf(p, w, -0.00417768164f);
        p = fmaf(p, w, 0.246640727f);
        p = fmaf(p, w, 1.50140941f);
    } else {
        w = __fsub_rn(__fsqrt_rn(w), 3.0f);
        p = -0.000200214257f;
        p = fmaf(p, w, 0.000100950558f);
        p = fmaf(p, w, 0.00134934322f);
        p = fmaf(p, w, -0.00367342844f);
        p = fmaf(p, w, 0.00573950773f);
        p = fmaf(p, w, -0.0076224613f);
        p = fmaf(p, w, 0.00943887047f);
        p = fmaf(p, w, 1.00167406f);
        p = fmaf(p, w, 2.83297682f);
    }
    return __fmul_rn(p, x);
}

// jax.random.normal scalar
__device__ __forceinline__ float nrm(K2 k) {
    float f = u01(k);
    const float lo = __uint_as_float(0xBF7FFFFFu);
    float v = __fadd_rn(__fmul_rn(f, 2.0f), lo);
    v = fmaxf(lo, v);
    return __fmul_rn(__uint_as_float(0x3FB504F3u), erfinv_xla(v));
}

// ------------------------- degree / norm ------------------------------------
__global__ void k_deg_init(int n) {
    int i = blockIdx.x * blockDim.x + threadIdx.x;
    if (i < n) g_deg[i] = 1.0f;
}
__global__ void k_deg_count(const int* __restrict__ dst, int E) {
    int e = blockIdx.x * blockDim.x + threadIdx.x;
    if (e < E) atomicAdd(&g_deg[dst[e]], 1.0f);
}
__global__ void k_dinv(int n) {
    int i = blockIdx.x * blockDim.x + threadIdx.x;
    if (i < n) g_dinv[i] = (float)(1.0 / sqrt((double)g_deg[i]));
}

// self-loop init: agg[i] = h[i] * dinv[i]^2
__global__ void k_self(int n4) {
    int idx = blockIdx.x * blockDim.x + threadIdx.x;
    if (idx >= n4) return;
    int node = idx >> 5;
    float di = g_dinv[node];
    float n2 = __fmul_rn(di, di);
    float4 v = ((const float4*)g_h)[idx];
    float4 o;
    o.x = __fmul_rn(v.x, n2); o.y = __fmul_rn(v.y, n2);
    o.z = __fmul_rn(v.z, n2); o.w = __fmul_rn(v.w, n2);
    ((float4*)g_agg)[idx] = o;
}

// edge scatter: one warp per edge, vector red.global.add.v4.f32
__global__ void k_scatter(const int* __restrict__ src, const int* __restrict__ dst, int E) {
    int e = blockIdx.x * 8 + (threadIdx.x >> 5);
    if (e >= E) return;
    int lane = threadIdx.x & 31;
    int s = __ldg(&src[e]);
    int d = __ldg(&dst[e]);
    float norm = __fmul_rn(g_dinv[s], g_dinv[d]);
    float4 v = *(const float4*)(g_h + (size_t)s * 128 + lane * 4);
    float* out = g_agg + (size_t)d * 128 + lane * 4;
    float m0 = __fmul_rn(v.x, norm);
    float m1 = __fmul_rn(v.y, norm);
    float m2 = __fmul_rn(v.z, norm);
    float m3 = __fmul_rn(v.w, norm);
    asm volatile("red.global.add.v4.f32 [%0], {%1,%2,%3,%4};"
                 :: "l"(out), "f"(m0), "f"(m1), "f"(m2), "f"(m3) : "memory");
}

// MLP1 input: g_h <- relu(agg + b_conv) + x   (overwrites g_h, dead after scatter)
__global__ void k_prep(const float* __restrict__ x, const float* __restrict__ bc, int n4) {
    int idx = blockIdx.x * blockDim.x + threadIdx.x;
    if (idx >= n4) return;
    int c4 = (idx & 31);
    float4 g = ((const float4*)g_agg)[idx];
    float4 xv = ((const float4*)x)[idx];
    float4 b = ((const float4*)bc)[c4];
    float4 o;
    o.x = __fadd_rn(fmaxf(__fadd_rn(g.x, b.x), 0.f), xv.x);
    o.y = __fadd_rn(fmaxf(__fadd_rn(g.y, b.y), 0.f), xv.y);
    o.z = __fadd_rn(fmaxf(__fadd_rn(g.z, b.z), 0.f), xv.z);
    o.w = __fadd_rn(fmaxf(__fadd_rn(g.w, b.w), 0.f), xv.w);
    ((float4*)g_h)[idx] = o;
}

// ------------------------- GEMM: double-buffered SGEMM ----------------------
// 128x128 block tile, 256 threads, 8x8 thread tile (split 4+4 cols), KB=8.
// EPI=0: C = A@W.  EPI=1: C = leaky(A@W + bout).
// Conflict-free smem: sA k-major pitch 132; W cols read as tx*4 and tx*4+64.
#define KB 8
#define PA 132

template<int K, int LDW, int LDA, int LDC, int EPI>
__global__ void __launch_bounds__(256) k_gemm(const float* __restrict__ A,
                                              const float* __restrict__ W,
                                              const float* __restrict__ bout,
                                              float* __restrict__ Cout, int N) {
    __shared__ float sA[2][KB][PA];
    __shared__ float sW[2][KB][128];

    const int t    = threadIdx.x;
    const int row0 = blockIdx.x * 128;
    const int c0   = blockIdx.y * 128;
    const int S    = K / KB;

    const int ar   = t >> 1;
    const int ak4  = (t & 1) * 4;
    const int wr   = t >> 5;
    const int wc4  = (t & 31) * 4;
    const int arow = row0 + ar;
    const bool aok = arow < N;

    const int tx = t & 15;
    const int ty = t >> 4;
    const int cx = tx * 4;          // cols cx..cx+3 and cx+64..cx+67
    const int r0 = ty * 8;

    float acc[8][8];
#pragma unroll
    for (int j = 0; j < 8; j++)
#pragma unroll
        for (int q = 0; q < 8; q++) acc[j][q] = 0.f;

    const float* Aptr = A + (size_t)arow * LDA + ak4;
    const float* Wptr = W + (size_t)wr * LDW + c0 + wc4;

    float4 va = make_float4(0.f, 0.f, 0.f, 0.f);
    if (aok) va = *(const float4*)(Aptr);
    float4 vw = *(const float4*)(Wptr);

    sA[0][ak4 + 0][ar] = va.x;
    sA[0][ak4 + 1][ar] = va.y;
    sA[0][ak4 + 2][ar] = va.z;
    sA[0][ak4 + 3][ar] = va.w;
    *(float4*)&sW[0][wr][wc4] = vw;
    __syncthreads();

    for (int s = 0; s < S; s++) {
        const int buf = s & 1;
        if (s + 1 < S) {
            int kc = (s + 1) * KB;
            if (aok) va = *(const float4*)(Aptr + kc);
            vw = *(const float4*)(Wptr + (size_t)kc * LDW);
        }
#pragma unroll
        for (int k = 0; k < KB; k++) {
            float4 a0 = *(const float4*)&sA[buf][k][r0];
            float4 a1 = *(const float4*)&sA[buf][k][r0 + 4];
            float4 w0 = *(const float4*)&sW[buf][k][cx];
            float4 w1 = *(const float4*)&sW[buf][k][cx + 64];
#pragma unroll
            for (int j = 0; j < 8; j++) {
                float av = (j < 4) ? ((j == 0) ? a0.x : (j == 1) ? a0.y : (j == 2) ? a0.z : a0.w)
                                   : ((j == 4) ? a1.x : (j == 5) ? a1.y : (j == 6) ? a1.z : a1.w);
                acc[j][0] = fmaf(av, w0.x, acc[j][0]);
                acc[j][1] = fmaf(av, w0.y, acc[j][1]);
                acc[j][2] = fmaf(av, w0.z, acc[j][2]);
                acc[j][3] = fmaf(av, w0.w, acc[j][3]);
                acc[j][4] = fmaf(av, w1.x, acc[j][4]);
                acc[j][5] = fmaf(av, w1.y, acc[j][5]);
                acc[j][6] = fmaf(av, w1.z, acc[j][6]);
                acc[j][7] = fmaf(av, w1.w, acc[j][7]);
            }
        }
        if (s + 1 < S) {
            const int nb = buf ^ 1;
            sA[nb][ak4 + 0][ar] = va.x;
            sA[nb][ak4 + 1][ar] = va.y;
            sA[nb][ak4 + 2][ar] = va.z;
            sA[nb][ak4 + 3][ar] = va.w;
            *(float4*)&sW[nb][wr][wc4] = vw;
        }
        __syncthreads();
    }

    float4 b0 = make_float4(0.f, 0.f, 0.f, 0.f);
    float4 b1v = b0;
    if (EPI) {
        b0  = *(const float4*)(bout + c0 + cx);
        b1v = *(const float4*)(bout + c0 + cx + 64);
    }
#pragma unroll
    for (int j = 0; j < 8; j++) {
        int row = row0 + r0 + j;
        if (row >= N) continue;
        float4 o0 = make_float4(acc[j][0], acc[j][1], acc[j][2], acc[j][3]);
        float4 o1 = make_float4(acc[j][4], acc[j][5], acc[j][6], acc[j][7]);
        if (EPI) {
            o0.x = __fadd_rn(o0.x, b0.x);  o0.x = (o0.x >= 0.f) ? o0.x : __fmul_rn(0.01f, o0.x);
            o0.y = __fadd_rn(o0.y, b0.y);  o0.y = (o0.y >= 0.f) ? o0.y : __fmul_rn(0.01f, o0.y);
            o0.z = __fadd_rn(o0.z, b0.z);  o0.z = (o0.z >= 0.f) ? o0.z : __fmul_rn(0.01f, o0.z);
            o0.w = __fadd_rn(o0.w, b0.w);  o0.w = (o0.w >= 0.f) ? o0.w : __fmul_rn(0.01f, o0.w);
            o1.x = __fadd_rn(o1.x, b1v.x); o1.x = (o1.x >= 0.f) ? o1.x : __fmul_rn(0.01f, o1.x);
            o1.y = __fadd_rn(o1.y, b1v.y); o1.y = (o1.y >= 0.f) ? o1.y : __fmul_rn(0.01f, o1.y);
            o1.z = __fadd_rn(o1.z, b1v.z); o1.z = (o1.z >= 0.f) ? o1.z : __fmul_rn(0.01f, o1.z);
            o1.w = __fadd_rn(o1.w, b1v.w); o1.w = (o1.w >= 0.f) ? o1.w : __fmul_rn(0.01f, o1.w);
        }
        *(float4*)(Cout + (size_t)row * LDC + c0 + cx)      = o0;
        *(float4*)(Cout + (size_t)row * LDC + c0 + cx + 64) = o1;
    }
}

// conc = softplus(h2 @ W3 + b3) + 1e-20   (warp per row)
__global__ void k_conc(const float* __restrict__ W3, const float* __restrict__ b3, int N) {
    int row = blockIdx.x * 8 + (threadIdx.x >> 5);
    if (row >= N) return;
    int lane = threadIdx.x & 31;
    const float4* hr = (const float4*)(g_h2 + (size_t)row * 256);
    const float4* w4 = (const float4*)W3;
    float s = 0.f;
#pragma unroll
    for (int j = lane; j < 64; j += 32) {
        float4 a = hr[j], w = w4[j];
        s = fmaf(a.x, w.x, s); s = fmaf(a.y, w.y, s);
        s = fmaf(a.z, w.z, s); s = fmaf(a.w, w.w, s);
    }
#pragma unroll
    for (int o = 16; o; o >>= 1) s += __shfl_xor_sync(0xFFFFFFFFu, s, o);
    if (lane == 0) {
        float z = __fadd_rn(s, b3[0]);
        double sp = fmax((double)z, 0.0) + log1p(exp(-fabs((double)z)));
        g_conc[row] = __fadd_rn((float)sp, 1e-20f);
    }
}

// ------------------------- loggamma sampler (jax _gamma_one) -----------------
__global__ void k_sample(int N) {
    int i = blockIdx.x * blockDim.x + threadIdx.x;
    if (i >= N) return;
    float alpha = g_conc[i];
    K2 key = split_big(K2{0u, 42u}, (unsigned)i);

    bool boost = (alpha >= 1.0f);
    float alpha_b = boost ? alpha : __fadd_rn(alpha, 1.0f);
    const float third = 0.3333333433f;
    float d = __fsub_rn(alpha_b, third);
    float c = __fdiv_rn(third, __fsqrt_rn(d));

    K2 k0, sub;
    split2(key, k0, sub);
    key = k0;
    float u_boost = u01(sub);

    float V;
    for (;;) {
        K2 nk, xk, uk;
        split3(key, nk, xk, uk);
        key = nk;
        float x, v;
        K2 kk = xk;
        do {
            K2 a, b;
            split2(kk, a, b);
            kk = a;
            x = nrm(b);
            v = __fadd_rn(1.0f, __fmul_rn(c, x));
        } while (v <= 0.0f);
        float X = __fmul_rn(x, x);
        V = __fmul_rn(__fmul_rn(v, v), v);
        float U = u01(uk);
        float sq = __fsub_rn(1.0f, __fmul_rn(0.0331f, __fmul_rn(X, X)));
        if (U < sq) break;
        float logU = (float)log((double)U);
        float logV = (float)log((double)V);
        float rhs = __fadd_rn(__fmul_rn(X, 0.5f),
                              __fmul_rn(d, __fadd_rn(__fsub_rn(1.0f, V), logV)));
        if (logU < rhs) break;
    }
    float log_sample = __fadd_rn((float)log((double)d), (float)log((double)V));
    float lg;
    if (boost) lg = log_sample;
    else {
        float lb = __fmul_rn((float)log1p(-(double)u_boost), __fdiv_rn(1.0f, alpha));
        lg = __fadd_rn(log_sample, lb);
    }
    g_lg[i] = lg;
}

// ------------------------- per-row finish: softmax + log_prob ----------------
__global__ void k_row(float* __restrict__ out, int N, int writeLP) {
    int b = blockIdx.x;
    int t = threadIdx.x;
    __shared__ float  rf[256];
    __shared__ double rd[256];
    const float* lg = g_lg   + (size_t)b * ADIM;
    const float* cc = g_conc + (size_t)b * ADIM;

    float m = -1e30f;
    for (int j = t; j < ADIM; j += 256) m = fmaxf(m, lg[j]);
    rf[t] = m; __syncthreads();
    for (int s = 128; s; s >>= 1) { if (t < s) rf[t] = fmaxf(rf[t], rf[t + s]); __syncthreads(); }
    m = rf[0]; __syncthreads();

    float se = 0.f;
    for (int j = t; j < ADIM; j += 256)
        se = __fadd_rn(se, (float)exp((double)__fsub_rn(lg[j], m)));
    rf[t] = se; __syncthreads();
    for (int s = 128; s; s >>= 1) { if (t < s) rf[t] = __fadd_rn(rf[t], rf[t + s]); __syncthreads(); }
    float lse = __fadd_rn((float)log((double)rf[0]), m);
    __syncthreads();

    double t1 = 0.0, t3 = 0.0, sc = 0.0;
    for (int j = t; j < ADIM; j += 256) {
        float af = (float)exp((double)__fsub_rn(lg[j], lse));
        out[(size_t)b * ADIM + j] = af;
        float cj = cc[j];
        t1 += (double)__fsub_rn(cj, 1.0f) * log((double)af);
        t3 += (double)lgammaf(cj);
        sc += (double)cj;
    }
    rd[t] = t1; __syncthreads();
    for (int s = 128; s; s >>= 1) { if (t < s) rd[t] += rd[t + s]; __syncthreads(); }
    t1 = rd[0]; __syncthreads();
    rd[t] = t3; __syncthreads();
    for (int s = 128; s; s >>= 1) { if (t < s) rd[t] += rd[t + s]; __syncthreads(); }
    t3 = rd[0]; __syncthreads();
    rd[t] = sc; __syncthreads();
    for (int s = 128; s; s >>= 1) { if (t < s) rd[t] += rd[t + s]; __syncthreads(); }
    sc = rd[0];

    if (t == 0 && writeLP) {
        float scf = (float)sc;
        double lp = t1 + lgamma((double)scf) - t3;
        out[(size_t)N + b] = (float)lp;
    }
}

// ------------------------- launch -------------------------------------------
extern "C" void kernel_launch(void* const* d_in, const int* in_sizes, int n_in,
                              void* d_out, int out_size) {
    const float* x      = (const float*)d_in[0];
    const float* W_conv = (const float*)d_in[1];
    const float* b_conv = (const float*)d_in[2];
    const float* W1     = (const float*)d_in[3];
    const float* b1     = (const float*)d_in[4];
    const float* W2     = (const float*)d_in[5];
    const float* b2     = (const float*)d_in[6];
    const float* W3     = (const float*)d_in[7];
    const float* b3     = (const float*)d_in[8];
    const int*   ei     = (const int*)d_in[9];
    float* out = (float*)d_out;

    int N = in_sizes[0] / 128;
    int E = in_sizes[9] / 2;
    int B = N / ADIM;
    const int* src = ei;
    const int* dst = ei + E;

    k_deg_init<<<(N + 255) / 256, 256>>>(N);
    k_deg_count<<<(E + 255) / 256, 256>>>(dst, E);
    k_dinv<<<(N + 255) / 256, 256>>>(N);

    float* gh = nullptr; float* gh1 = nullptr; float* gh2 = nullptr;
    cudaGetSymbolAddress((void**)&gh,  g_h);
    cudaGetSymbolAddress((void**)&gh1, g_h1);
    cudaGetSymbolAddress((void**)&gh2, g_h2);

    dim3 g0((N + 127) / 128, 1), g1((N + 127) / 128, 2);
    // h = x @ Wc
    k_gemm<128,128,128,128,0><<<g0, 256>>>(x, W_conv, nullptr, gh, N);
    k_self<<<(N * 32 + 255) / 256, 256>>>(N * 32);
    k_scatter<<<(E + 7) / 8, 256>>>(src, dst, E);
    // g_h <- relu(agg + b_conv) + x
    k_prep<<<(N * 32 + 255) / 256, 256>>>(x, b_conv, N * 32);
    // h1 = leaky(g_h @ W1 + b1)
    k_gemm<128,256,128,256,1><<<g1, 256>>>(gh, W1, b1, gh1, N);
    // h2 = leaky(h1 @ W2 + b2)
    k_gemm<256,256,256,256,1><<<g1, 256>>>(gh1, W2, b2, gh2, N);
    k_conc<<<(N + 7) / 8, 256>>>(W3, b3, N);
    k_sample<<<(N + 127) / 128, 128>>>(N);
    int writeLP = (out_size >= N + B) ? 1 : 0;
    k_row<<<B, 256>>>(out, N, writeLP);
}